// round 1
// baseline (speedup 1.0000x reference)
#include <cuda_runtime.h>

// CTC forward loss (alpha recursion).
// Shapes fixed by the dataset: B=256, T=1024, C=128, U=128, S=2U+1=257, blank=C-1.
// Inputs (metadata order): d_in[0] = y_true (int32, B*U), d_in[1] = y_pred (float32, B*T*C, softmax probs).
// Output: d_out (float32, B) = -log p(y|x).

#define T_DIM 1024
#define C_DIM 128
#define U_DIM 128
#define S_DIM 257          // 2U+1
#define BLANK 127          // C-1
#define NEGV  (-1e30f)
#define EPSV  (1e-7f)
#define NTHREADS 288       // 9 warps: warps 0-3 also produce per-class logs

__global__ __launch_bounds__(NTHREADS)
void ctc_alpha_kernel(const int* __restrict__ y_true,
                      const float* __restrict__ y_pred,
                      float* __restrict__ out)
{
    __shared__ float alphaA[S_DIM];
    __shared__ float alphaB[S_DIM];
    __shared__ float logc[2][C_DIM];   // per-class log(p+eps), double-buffered by t parity

    const int b   = blockIdx.x;
    const int tid = threadIdx.x;
    const float* __restrict__ P = y_pred + (size_t)b * T_DIM * C_DIM;
    const int*   __restrict__ Y = y_true + (size_t)b * U_DIM;

    // Per-thread static state info: extended label and "skip" (a2) permission.
    int  ext_s = BLANK;
    bool allow = false;
    if (tid < S_DIM) {
        if (tid & 1) {
            const int u = tid >> 1;
            ext_s = Y[u];
            allow = (tid >= 3) && (ext_s != Y[u - 1]) && (ext_s != BLANK);
        }
    }

    // t = 0 init: alpha0[0] = log p(blank|0), alpha0[1] = log p(y0|0), else NEG.
    if (tid < S_DIM) {
        float a0 = NEGV;
        if (tid <= 1) a0 = __logf(P[ext_s] + EPSV);
        alphaA[tid] = a0;
    }

    // Software pipeline: logc for row 1 now; rows 2,3 prefetched into registers.
    float p_next = 0.f, p_next2 = 0.f;
    if (tid < C_DIM) {
        logc[1][tid] = __logf(P[1 * C_DIM + tid] + EPSV);   // buffer (t=1)&1 = 1
        p_next  = P[2 * C_DIM + tid];
        p_next2 = P[3 * C_DIM + tid];
    }
    __syncthreads();

    float* cur = alphaA;
    float* nxt = alphaB;

    #pragma unroll 1
    for (int t = 1; t < T_DIM; ++t) {
        // Produce logc for row t+1 (buffer (t+1)&1) — consumed next iteration.
        // Disjoint from this iteration's read buffer (t&1): one barrier per step.
        if (tid < C_DIM) {
            if (t + 1 < T_DIM) {
                logc[(t + 1) & 1][tid] = __logf(p_next + EPSV);
                p_next = p_next2;
                const int tload = t + 3;
                if (tload < T_DIM) p_next2 = P[tload * C_DIM + tid];
            }
        }

        if (tid < S_DIM) {
            const float a  = cur[tid];
            const float a1 = (tid >= 1) ? cur[tid - 1] : NEGV;
            const float a2 = allow ? cur[tid - 2] : NEGV;

            // lse3 with the max contributing exactly 1.0 (saves one MUFU exp):
            const float hi = fmaxf(a, a1);
            const float lo = fminf(a, a1);
            const float m  = fmaxf(hi, a2);
            const float s2 = fmaxf(fminf(hi, a2), lo);   // 2nd largest
            const float s3 = fminf(lo, a2);              // 3rd largest
            const float v  = 1.0f + __expf(s2 - m) + __expf(s3 - m);

            nxt[tid] = m + __logf(v) + logc[t & 1][ext_s];
        }
        __syncthreads();
        float* tmp = cur; cur = nxt; nxt = tmp;
    }

    if (tid == 0) {
        const float a  = cur[S_DIM - 1];
        const float bb = cur[S_DIM - 2];
        const float m  = fmaxf(a, bb);
        const float ll = m + __logf(__expf(a - m) + __expf(bb - m));
        out[b] = -ll;
    }
}

extern "C" void kernel_launch(void* const* d_in, const int* in_sizes, int n_in,
                              void* d_out, int out_size)
{
    const int*   y_true = (const int*)d_in[0];
    const float* y_pred = (const float*)d_in[1];
    float*       out    = (float*)d_out;

    const int B = out_size;   // 256
    ctc_alpha_kernel<<<B, NTHREADS>>>(y_true, y_pred, out);
}

// round 4
// speedup vs baseline: 5.1615x; 5.1615x over previous
#include <cuda_runtime.h>
#include <cstdint>
#include <math.h>

// CTC forward loss, linear-domain alpha recursion with per-lane block-floating-point.
// B=256, T=1024, C=128, U=128, S=257, blank=127.
// d_in[0] = y_true (int32 B*U), d_in[1] = y_pred (float32 B*T*C). out: (B) fp32 = -log p.
//
// One warp per batch. Lane l owns labels u=4l..4l+3 and blanks u=4l..4l+3
// (lane 31 additionally blank u=128). Linear recurrence:
//   blank u : b[u] <- (b[u] + L[u-1]) * (p_blank + eps)
//   label u : L[u] <- (L[u] + b[u] + allow_u * L[u-1]) * (p[y_u] + eps)
// Cross-lane: lane l-1's L3 via shfl, rescaled by exact 2^(F_{l-1}-F_l).
// Each lane carries integer exponent E; renormalized every 4 steps; lane bases
// agreed via decayed prefix-max scan (decay 96/lane) so scale factors never overflow
// and values are only flushed when >=2^96 below incoming mass.

#define T_DIM 1024
#define C_DIM 128
#define BLANK 127
#define EPSV  1e-7f
#define RING  16
#define SENT  (-(1 << 28))
#define DECAY 96

__device__ __forceinline__ uint32_t smem_u32(const void* p) {
    uint32_t a;
    asm("{ .reg .u64 t; cvta.to.shared.u64 t, %1; cvt.u32.u64 %0, t; }" : "=r"(a) : "l"(p));
    return a;
}
__device__ __forceinline__ void cp_async16(uint32_t dst, const void* src) {
    asm volatile("cp.async.cg.shared.global [%0], [%1], 16;" :: "r"(dst), "l"(src));
}
__device__ __forceinline__ void cp_commit() {
    asm volatile("cp.async.commit_group;" ::: "memory");
}
__device__ __forceinline__ void cp_wait2() {
    asm volatile("cp.async.wait_group 2;" ::: "memory");
}

// Exact 2^d as float; d <= -127 -> 0, d clamped at 127.
__device__ __forceinline__ float pow2f(int d) {
    d = min(d, 127);
    return (d <= -127) ? 0.f : __int_as_float((d + 127) << 23);
}

__global__ void __launch_bounds__(32)
ctc_blkfloat_kernel(const int* __restrict__ y_true,
                    const float* __restrict__ y_pred,
                    float* __restrict__ out)
{
    __shared__ float ring[RING][C_DIM];   // 8 KB

    const int b = blockIdx.x;
    const int l = threadIdx.x;
    const float* __restrict__ P = y_pred + (size_t)b * T_DIM * C_DIM;
    const int*   __restrict__ Y = y_true + (size_t)b * 128;

    const int y0 = Y[4 * l + 0];
    const int y1 = Y[4 * l + 1];
    const int y2 = Y[4 * l + 2];
    const int y3 = Y[4 * l + 3];
    const int yprev = (l == 0) ? -1 : Y[4 * l - 1];
    const bool al0 = (l > 0) && (y0 != yprev);
    const bool al1 = (y1 != y0);
    const bool al2 = (y2 != y1);
    const bool al3 = (y3 != y2);

    const uint32_t rbase_sh = smem_u32(ring);
    const uint32_t lane_off = l * 16;

    // Prologue: prefetch rows 0..11 as 3 groups of 4.
    #pragma unroll
    for (int g = 0; g < 3; ++g) {
        #pragma unroll
        for (int j = 0; j < 4; ++j) {
            const int r = g * 4 + j;
            cp_async16(rbase_sh + (uint32_t)(r & (RING - 1)) * (C_DIM * 4) + lane_off,
                       P + (size_t)r * C_DIM + l * 4);
        }
        cp_commit();
    }

    // t = 0 init: only states 0 (blank u=0) and 1 (label u=0), both on lane 0.
    float b0 = 0.f, b1 = 0.f, b2 = 0.f, b3 = 0.f, b4 = 0.f;
    float L0 = 0.f, L1 = 0.f, L2 = 0.f, L3 = 0.f;
    if (l == 0) {
        b0 = P[BLANK] + EPSV;
        L0 = P[y0] + EPSV;
    }
    int   E        = (l == 0) ? 0 : SENT;   // lane exponent (values are v * 2^E)
    float scale_in = 0.f;                   // 2^(E_nb - E); 0 until first normalization

    #pragma unroll 1
    for (int k = 0; k < T_DIM / 4; ++k) {
        cp_wait2();            // rows <= 4k+3 resident (3 groups max pending)
        __syncwarp();
        {   // prefetch rows 4k+12..4k+15 into slots of consumed rows 4k-4..4k-1
            const int r0 = 4 * k + 12;
            if (r0 < T_DIM) {
                #pragma unroll
                for (int j = 0; j < 4; ++j) {
                    const int r = r0 + j;
                    cp_async16(rbase_sh + (uint32_t)(r & (RING - 1)) * (C_DIM * 4) + lane_off,
                               P + (size_t)r * C_DIM + l * 4);
                }
            }
            cp_commit();
        }

        #pragma unroll
        for (int j = 0; j < 4; ++j) {
            const int t = 4 * k + j;
            if (t != 0) {
                const float* row = ring[t & (RING - 1)];
                const float pbe = row[BLANK] + EPSV;
                const float p0 = row[y0] + EPSV;
                const float p1 = row[y1] + EPSV;
                const float p2 = row[y2] + EPSV;
                const float p3 = row[y3] + EPSV;

                // neighbor label L[4l-1], converted into this lane's scale (exact pow2)
                const float ap = __shfl_up_sync(0xffffffffu, L3, 1) * scale_in;

                const float nL0 = (L0 + b0 + (al0 ? ap : 0.f)) * p0;
                const float nL1 = (L1 + b1 + (al1 ? L0 : 0.f)) * p1;
                const float nL2 = (L2 + b2 + (al2 ? L1 : 0.f)) * p2;
                const float nL3 = (L3 + b3 + (al3 ? L2 : 0.f)) * p3;
                const float nb0 = (b0 + ap) * pbe;
                const float nb1 = (b1 + L0) * pbe;
                const float nb2 = (b2 + L1) * pbe;
                const float nb3 = (b3 + L2) * pbe;
                const float nb4 = (l == 31) ? (b4 + L3) * pbe : 0.f;

                L0 = nL0; L1 = nL1; L2 = nL2; L3 = nL3;
                b0 = nb0; b1 = nb1; b2 = nb2; b3 = nb3; b4 = nb4;
            }
        }

        // ---- per-lane renormalization + base agreement (every 4 steps) ----
        {
            const float m = fmaxf(fmaxf(fmaxf(L0, L1), fmaxf(L2, L3)),
                                  fmaxf(fmaxf(b0, b1), fmaxf(b2, fmaxf(b3, b4))));
            // absolute exponent of lane max (SENT if lane has no mass)
            int Ep = SENT;
            if (m > 0.f)
                Ep = E + ((__float_as_int(m) >> 23) & 255) - 127;

            // decayed prefix max: F_l = max_{j<=l} (Ep_j - DECAY*(l-j))
            int F = Ep;
            #pragma unroll
            for (int off = 1; off <= 16; off <<= 1) {
                const int o = __shfl_up_sync(0xffffffffu, F, off);
                if (l >= off) F = max(F, o - DECAY * off);
            }
            const int Fnb = __shfl_up_sync(0xffffffffu, F, 1);   // F_{l-1}

            const float sc = pow2f(E - F);    // rebase own values (exact)
            L0 *= sc; L1 *= sc; L2 *= sc; L3 *= sc;
            b0 *= sc; b1 *= sc; b2 *= sc; b3 *= sc; b4 *= sc;
            E = F;
            scale_in = (l == 0) ? 0.f : pow2f(Fnb - F);  // bounded: Fnb - F <= DECAY
        }
    }

    // Final: state S-1 (blank u=128 -> b4) and S-2 (label u=127 -> L3), lane 31.
    if (l == 31) {
        const double ll = (double)E * 0.6931471805599453
                        + log((double)L3 + (double)b4);
        out[b] = (float)(-ll);
    }
}

extern "C" void kernel_launch(void* const* d_in, const int* in_sizes, int n_in,
                              void* d_out, int out_size)
{
    const int*   y_true = (const int*)d_in[0];
    const float* y_pred = (const float*)d_in[1];
    float*       out    = (float*)d_out;
    ctc_blkfloat_kernel<<<out_size, 32>>>(y_true, y_pred, out);
}

// round 6
// speedup vs baseline: 9.1583x; 1.7744x over previous
#include <cuda_runtime.h>
#include <cstdint>
#include <math.h>

// CTC forward loss via exact forward/backward split at T/2.
// B=256, T=1024, C=128, U=128, S=257, blank=127.
// d_in[0]=y_true (int32 B*128), d_in[1]=y_pred (fp32 B*T*C). out: (B) fp32 = -log p.
//
// Kernel 1 (grid 512): even blocks run forward alpha over frames 0..511,
// odd blocks run backward beta over frames 1023..512. One warp each; lane l
// owns labels/blanks u=4l..4l+3 (lane 31 also blank u=128). Linear domain with
// per-lane block floating point: integer exponent E, renorm EVERY 4 steps
// (load-bearing: a 4-step window means imported mass crosses at most ONE lane
// boundary before re-anchoring -> values bounded by ~2^103, no fp32 overflow;
// an 8-step window double-scales by 2^192 -> inf), decayed prefix-max base
// agreement (DECAY=96/lane); all scaling exact powers of two.
// Kernel 2 (grid 256): ll = sum_s alpha_511[s]*beta_511[s] with exponent align.

#define T_DIM  1024
#define HALF_T 512
#define C_DIM  128
#define BLANK  127
#define EPSV   1e-7f
#define RING   16
#define SENT   (-(1 << 28))
#define DECAY  96
#define B_DIM  256

__device__ float g_vals[2][B_DIM][32][9];   // [dir][batch][lane][state]: b0..b3,L0..L3,b4
__device__ int   g_exps[2][B_DIM][32];

__device__ __forceinline__ uint32_t smem_u32(const void* p) {
    uint32_t a;
    asm("{ .reg .u64 t; cvta.to.shared.u64 t, %1; cvt.u32.u64 %0, t; }" : "=r"(a) : "l"(p));
    return a;
}
__device__ __forceinline__ void cp_async16(uint32_t dst, const void* src) {
    asm volatile("cp.async.cg.shared.global [%0], [%1], 16;" :: "r"(dst), "l"(src));
}
__device__ __forceinline__ void cp_commit() {
    asm volatile("cp.async.commit_group;" ::: "memory");
}
__device__ __forceinline__ void cp_wait2() {
    asm volatile("cp.async.wait_group 2;" ::: "memory");
}
__device__ __forceinline__ float pow2f(int d) {   // exact 2^d; d<=-127 -> 0
    d = min(d, 127);
    return (d <= -127) ? 0.f : __int_as_float((d + 127) << 23);
}

__global__ void __launch_bounds__(32)
ctc_half_kernel(const int* __restrict__ y_true,
                const float* __restrict__ y_pred)
{
    __shared__ float ring[RING][C_DIM];

    const int b   = blockIdx.x >> 1;
    const int dir = blockIdx.x & 1;       // 0 = forward, 1 = backward
    const int l   = threadIdx.x;
    const float* __restrict__ P = y_pred + (size_t)b * T_DIM * C_DIM;
    const int*   __restrict__ Y = y_true + (size_t)b * 128;

    const int y0 = Y[4 * l + 0];
    const int y1 = Y[4 * l + 1];
    const int y2 = Y[4 * l + 2];
    const int y3 = Y[4 * l + 3];

    const uint32_t rbase_sh = smem_u32(ring);
    const uint32_t lane_off = l * 16;

    float b0 = 0.f, b1 = 0.f, b2 = 0.f, b3 = 0.f, b4 = 0.f;
    float L0 = 0.f, L1 = 0.f, L2 = 0.f, L3 = 0.f;
    int   E;
    float scale_in = 0.f;

    if (dir == 0) {
        // ---------------- FORWARD: frames 0..511 -> alpha_511 ----------------
        const int yprev = (l == 0) ? -1 : Y[4 * l - 1];
        const float al0f = ((l > 0) && (y0 != yprev)) ? 1.f : 0.f;
        const float al1f = (y1 != y0) ? 1.f : 0.f;
        const float al2f = (y2 != y1) ? 1.f : 0.f;
        const float al3f = (y3 != y2) ? 1.f : 0.f;

        #pragma unroll
        for (int g = 0; g < 3; ++g) {
            #pragma unroll
            for (int j = 0; j < 4; ++j) {
                const int r = g * 4 + j;
                cp_async16(rbase_sh + (uint32_t)(r & (RING - 1)) * (C_DIM * 4) + lane_off,
                           P + (size_t)r * C_DIM + l * 4);
            }
            cp_commit();
        }

        if (l == 0) { b0 = P[BLANK] + EPSV; L0 = P[y0] + EPSV; }
        E = (l == 0) ? 0 : SENT;

        #pragma unroll 1
        for (int k = 0; k < HALF_T / 4; ++k) {
            cp_wait2();
            __syncwarp();
            {
                const int r0 = 4 * k + 12;
                if (r0 < HALF_T) {
                    #pragma unroll
                    for (int j = 0; j < 4; ++j) {
                        const int r = r0 + j;
                        cp_async16(rbase_sh + (uint32_t)(r & (RING - 1)) * (C_DIM * 4) + lane_off,
                                   P + (size_t)r * C_DIM + l * 4);
                    }
                }
                cp_commit();
            }

            #pragma unroll
            for (int j = 0; j < 4; ++j) {
                const int t = 4 * k + j;
                if (t != 0) {
                    const float* row = ring[t & (RING - 1)];
                    const float pbe = row[BLANK] + EPSV;
                    const float p0 = row[y0] + EPSV;
                    const float p1 = row[y1] + EPSV;
                    const float p2 = row[y2] + EPSV;
                    const float p3 = row[y3] + EPSV;

                    // lane0: scale_in==0 forever -> ap==0
                    const float ap = __shfl_up_sync(0xffffffffu, L3, 1) * scale_in;

                    const float nL0 = __fmaf_rn(al0f, ap, L0 + b0) * p0;
                    const float nL1 = __fmaf_rn(al1f, L0, L1 + b1) * p1;
                    const float nL2 = __fmaf_rn(al2f, L1, L2 + b2) * p2;
                    const float nL3 = __fmaf_rn(al3f, L2, L3 + b3) * p3;
                    const float nb0 = (b0 + ap) * pbe;
                    const float nb1 = (b1 + L0) * pbe;
                    const float nb2 = (b2 + L1) * pbe;
                    const float nb3 = (b3 + L2) * pbe;
                    const float nb4 = (l == 31) ? (b4 + L3) * pbe : 0.f;

                    L0 = nL0; L1 = nL1; L2 = nL2; L3 = nL3;
                    b0 = nb0; b1 = nb1; b2 = nb2; b3 = nb3; b4 = nb4;
                }
            }

            // renorm EVERY 4-step block (overflow-safety critical)
            {
                const float m = fmaxf(fmaxf(fmaxf(L0, L1), fmaxf(L2, L3)),
                                      fmaxf(fmaxf(b0, b1), fmaxf(b2, fmaxf(b3, b4))));
                int Ep = SENT;
                if (m > 0.f) Ep = E + ((__float_as_int(m) >> 23) & 255) - 127;
                int F = Ep;
                #pragma unroll
                for (int off = 1; off <= 16; off <<= 1) {
                    const int o = __shfl_up_sync(0xffffffffu, F, off);
                    if (l >= off) F = max(F, o - DECAY * off);
                }
                const int Fnb = __shfl_up_sync(0xffffffffu, F, 1);
                const float sc = pow2f(E - F);
                L0 *= sc; L1 *= sc; L2 *= sc; L3 *= sc;
                b0 *= sc; b1 *= sc; b2 *= sc; b3 *= sc; b4 *= sc;
                E = F;
                scale_in = (l == 0) ? 0.f : pow2f(Fnb - F);
            }
        }
    } else {
        // ---------------- BACKWARD: frames 1023..512 -> beta_511 ----------------
        const float al1f = (y1 != y0) ? 1.f : 0.f;
        const float al2f = (y2 != y1) ? 1.f : 0.f;
        const float al3f = (y3 != y2) ? 1.f : 0.f;
        const int   ynx  = (l < 31) ? Y[4 * l + 4] : 0;           // label u=4(l+1)
        const float alnf = ((l < 31) && (ynx != y3)) ? 1.f : 0.f; // allow into next lane's L0

        #pragma unroll
        for (int g = 0; g < 3; ++g) {
            #pragma unroll
            for (int j = 0; j < 4; ++j) {
                const int f = 1023 - (g * 4 + j);
                cp_async16(rbase_sh + (uint32_t)(f & (RING - 1)) * (C_DIM * 4) + lane_off,
                           P + (size_t)f * C_DIM + l * 4);
            }
            cp_commit();
        }

        if (l == 31) { L3 = 1.f; b4 = 1.f; }   // beta_{1023}: states 255, 256
        E = (l == 31) ? 0 : SENT;

        #pragma unroll 1
        for (int k = 0; k < HALF_T / 4; ++k) {
            cp_wait2();
            __syncwarp();
            {
                const int i0 = 4 * k + 12;
                if (i0 < HALF_T) {
                    #pragma unroll
                    for (int j = 0; j < 4; ++j) {
                        const int f = 1023 - (i0 + j);
                        cp_async16(rbase_sh + (uint32_t)(f & (RING - 1)) * (C_DIM * 4) + lane_off,
                                   P + (size_t)f * C_DIM + l * 4);
                    }
                }
                cp_commit();
            }

            #pragma unroll
            for (int j = 0; j < 4; ++j) {
                const int f = 1023 - (4 * k + j);
                const float* row = ring[f & (RING - 1)];
                const float pbe = row[BLANK] + EPSV;
                const float p0 = row[y0] + EPSV;
                const float p1 = row[y1] + EPSV;
                const float p2 = row[y2] + EPSV;
                const float p3 = row[y3] + EPSV;
                const float pyn = row[ynx] + EPSV;

                // previous-step beta b0/L0 from lane l+1 (lane31 gets garbage, masked)
                const float bn = __shfl_down_sync(0xffffffffu, b0, 1);
                const float Ln = __shfl_down_sync(0xffffffffu, L0, 1);

                const float gb0 = b0 * pbe, gb1 = b1 * pbe, gb2 = b2 * pbe, gb3 = b3 * pbe;
                const float gb4 = b4 * pbe;
                const float gL0 = L0 * p0, gL1 = L1 * p1, gL2 = L2 * p2, gL3 = L3 * p3;

                const float gbn = bn * scale_in * pbe;
                const float gLn = Ln * scale_in * pyn;
                const float tb  = (l == 31) ? gb4 : gbn;
                const float tL  = (l == 31) ? 0.f : alnf * gLn;

                const float nb0 = gb0 + gL0;
                const float nb1 = gb1 + gL1;
                const float nb2 = gb2 + gL2;
                const float nb3 = gb3 + gL3;
                const float nL0 = __fmaf_rn(al1f, gL1, gL0 + gb1);
                const float nL1 = __fmaf_rn(al2f, gL2, gL1 + gb2);
                const float nL2 = __fmaf_rn(al3f, gL3, gL2 + gb3);
                const float nL3 = gL3 + tb + tL;

                L0 = nL0; L1 = nL1; L2 = nL2; L3 = nL3;
                b0 = nb0; b1 = nb1; b2 = nb2; b3 = nb3; b4 = gb4;
            }

            // renorm EVERY 4-step block (overflow-safety critical)
            {
                const float m = fmaxf(fmaxf(fmaxf(L0, L1), fmaxf(L2, L3)),
                                      fmaxf(fmaxf(b0, b1), fmaxf(b2, fmaxf(b3, b4))));
                int Ep = SENT;
                if (m > 0.f) Ep = E + ((__float_as_int(m) >> 23) & 255) - 127;
                int F = Ep;
                #pragma unroll
                for (int off = 1; off <= 16; off <<= 1) {
                    const int o = __shfl_down_sync(0xffffffffu, F, off);
                    if (l + off < 32) F = max(F, o - DECAY * off);
                }
                const int Fnb = __shfl_down_sync(0xffffffffu, F, 1);
                const float sc = pow2f(E - F);
                L0 *= sc; L1 *= sc; L2 *= sc; L3 *= sc;
                b0 *= sc; b1 *= sc; b2 *= sc; b3 *= sc; b4 *= sc;
                E = F;
                scale_in = (l == 31) ? 0.f : pow2f(Fnb - F);
            }
        }
    }

    // Store per-lane state vector + exponent.
    float* dst = g_vals[dir][b][l];
    dst[0] = b0; dst[1] = b1; dst[2] = b2; dst[3] = b3;
    dst[4] = L0; dst[5] = L1; dst[6] = L2; dst[7] = L3;
    dst[8] = b4;
    g_exps[dir][b][l] = E;
}

__global__ void __launch_bounds__(32)
ctc_combine_kernel(float* __restrict__ out)
{
    const int b = blockIdx.x;
    const int l = threadIdx.x;

    const float* a = g_vals[0][b][l];
    const float* c = g_vals[1][b][l];
    float s = 0.f;
    #pragma unroll
    for (int i = 0; i < 9; ++i) s += a[i] * c[i];
    int X = g_exps[0][b][l] + g_exps[1][b][l];
    if (!(s > 0.f)) { s = 0.f; X = SENT * 2; }

    int M = X;
    #pragma unroll
    for (int off = 16; off; off >>= 1)
        M = max(M, __shfl_xor_sync(0xffffffffu, M, off));

    float v = s * pow2f(X - M);
    #pragma unroll
    for (int off = 16; off; off >>= 1)
        v += __shfl_xor_sync(0xffffffffu, v, off);

    if (l == 0)
        out[b] = (float)(-((double)M * 0.6931471805599453 + log((double)v)));
}

extern "C" void kernel_launch(void* const* d_in, const int* in_sizes, int n_in,
                              void* d_out, int out_size)
{
    const int*   y_true = (const int*)d_in[0];
    const float* y_pred = (const float*)d_in[1];
    float*       out    = (float*)d_out;
    ctc_half_kernel<<<2 * B_DIM, 32>>>(y_true, y_pred);
    ctc_combine_kernel<<<B_DIM, 32>>>(out);
}

// round 8
// speedup vs baseline: 9.6015x; 1.0484x over previous
#include <cuda_runtime.h>
#include <cstdint>
#include <math.h>

// CTC forward loss via exact forward/backward split at T/2, fused combine.
// B=256, T=1024, C=128, U=128, S=257, blank=127.
// d_in[0]=y_true (int32 B*128), d_in[1]=y_pred (fp32 B*T*C). out: (B) fp32 = -log p.
//
// Grid 512: even blocks run forward alpha over frames 0..511, odd blocks run
// backward beta over frames 1023..512. One warp each; lane l owns labels/blanks
// u=4l..4l+3 (lane 31 also blank u=128). Linear domain, per-lane block float:
// integer exponent E, renorm every 4 steps (exactly safe: imported mass takes 4
// steps to traverse a lane, so at most one pow2 scale crossing per window),
// decayed prefix-max base agreement (DECAY=96/lane, 3-shfl scan: frontier
// advances <=2 lanes/window, coverage 7 is ample). All scaling exact pow2.
// The second block of each (fwd,bwd) pair to finish (atomic counter, parity
// self-resets across launches) computes ll = sum_s alpha*beta and writes out.

#define T_DIM  1024
#define HALF_T 512
#define C_DIM  128
#define BLANK  127
#define EPSV   1e-7f
#define RING   16
#define SENT   (-(1 << 28))
#define DECAY  96
#define B_DIM  256

__device__ float g_vals[2][B_DIM][32][9];   // [dir][batch][lane]: b0..b3,L0..L3,b4
__device__ int   g_exps[2][B_DIM][32];
__device__ int   g_done[B_DIM];             // zero-init; +2 per batch per launch

__device__ __forceinline__ uint32_t smem_u32(const void* p) {
    uint32_t a;
    asm("{ .reg .u64 t; cvta.to.shared.u64 t, %1; cvt.u32.u64 %0, t; }" : "=r"(a) : "l"(p));
    return a;
}
__device__ __forceinline__ void cp_async16(uint32_t dst, const void* src) {
    asm volatile("cp.async.cg.shared.global [%0], [%1], 16;" :: "r"(dst), "l"(src));
}
__device__ __forceinline__ void cp_commit() {
    asm volatile("cp.async.commit_group;" ::: "memory");
}
__device__ __forceinline__ void cp_wait2() {
    asm volatile("cp.async.wait_group 2;" ::: "memory");
}
__device__ __forceinline__ float pow2f(int d) {   // exact 2^d; d<=-127 -> 0
    d = min(d, 127);
    return (d <= -127) ? 0.f : __int_as_float((d + 127) << 23);
}

__global__ void __launch_bounds__(32)
ctc_fused_kernel(const int* __restrict__ y_true,
                 const float* __restrict__ y_pred,
                 float* __restrict__ out)
{
    __shared__ float ring[RING][C_DIM];

    const int b   = blockIdx.x >> 1;
    const int dir = blockIdx.x & 1;       // 0 = forward, 1 = backward
    const int l   = threadIdx.x;
    const float* __restrict__ P = y_pred + (size_t)b * T_DIM * C_DIM;
    const int*   __restrict__ Y = y_true + (size_t)b * 128;

    const int y0 = Y[4 * l + 0];
    const int y1 = Y[4 * l + 1];
    const int y2 = Y[4 * l + 2];
    const int y3 = Y[4 * l + 3];

    const uint32_t rbase_sh = smem_u32(ring);
    const uint32_t lane_off = l * 16;

    float b0 = 0.f, b1 = 0.f, b2 = 0.f, b3 = 0.f, b4 = 0.f;
    float L0 = 0.f, L1 = 0.f, L2 = 0.f, L3 = 0.f;
    int   E;
    float scale_in = 0.f;

    if (dir == 0) {
        // ---------------- FORWARD: frames 0..511 -> alpha_511 ----------------
        const int yprev = (l == 0) ? -1 : Y[4 * l - 1];
        const float al0f = ((l > 0) && (y0 != yprev)) ? 1.f : 0.f;
        const float al1f = (y1 != y0) ? 1.f : 0.f;
        const float al2f = (y2 != y1) ? 1.f : 0.f;
        const float al3f = (y3 != y2) ? 1.f : 0.f;

        #pragma unroll
        for (int g = 0; g < 3; ++g) {
            #pragma unroll
            for (int j = 0; j < 4; ++j) {
                const int r = g * 4 + j;
                cp_async16(rbase_sh + (uint32_t)(r & (RING - 1)) * (C_DIM * 4) + lane_off,
                           P + (size_t)r * C_DIM + l * 4);
            }
            cp_commit();
        }

        if (l == 0) { b0 = P[BLANK] + EPSV; L0 = P[y0] + EPSV; }
        E = (l == 0) ? 0 : SENT;

        #pragma unroll 1
        for (int k = 0; k < HALF_T / 4; ++k) {
            cp_wait2();
            __syncwarp();
            {
                const int r0 = 4 * k + 12;
                if (r0 < HALF_T) {
                    #pragma unroll
                    for (int j = 0; j < 4; ++j) {
                        const int r = r0 + j;
                        cp_async16(rbase_sh + (uint32_t)(r & (RING - 1)) * (C_DIM * 4) + lane_off,
                                   P + (size_t)r * C_DIM + l * 4);
                    }
                }
                cp_commit();
            }

            #pragma unroll
            for (int j = 0; j < 4; ++j) {
                const int t = 4 * k + j;
                if (t != 0) {
                    const float* row = ring[t & (RING - 1)];
                    const float pbe = row[BLANK] + EPSV;
                    const float p0 = row[y0] + EPSV;
                    const float p1 = row[y1] + EPSV;
                    const float p2 = row[y2] + EPSV;
                    const float p3 = row[y3] + EPSV;

                    // lane0: scale_in==0 forever -> ap==0
                    const float ap = __shfl_up_sync(0xffffffffu, L3, 1) * scale_in;

                    const float nL0 = __fmaf_rn(al0f, ap, L0 + b0) * p0;
                    const float nL1 = __fmaf_rn(al1f, L0, L1 + b1) * p1;
                    const float nL2 = __fmaf_rn(al2f, L1, L2 + b2) * p2;
                    const float nL3 = __fmaf_rn(al3f, L2, L3 + b3) * p3;
                    const float nb0 = (b0 + ap) * pbe;
                    const float nb1 = (b1 + L0) * pbe;
                    const float nb2 = (b2 + L1) * pbe;
                    const float nb3 = (b3 + L2) * pbe;
                    const float nb4 = (l == 31) ? (b4 + L3) * pbe : 0.f;

                    L0 = nL0; L1 = nL1; L2 = nL2; L3 = nL3;
                    b0 = nb0; b1 = nb1; b2 = nb2; b3 = nb3; b4 = nb4;
                }
            }

            // renorm every 4-step window (overflow-safety critical)
            {
                const float m = fmaxf(fmaxf(fmaxf(L0, L1), fmaxf(L2, L3)),
                                      fmaxf(fmaxf(b0, b1), fmaxf(b2, fmaxf(b3, b4))));
                int Ep = SENT;
                if (m > 0.f) Ep = E + ((__float_as_int(m) >> 23) & 255) - 127;
                int F = Ep;
                #pragma unroll
                for (int off = 1; off <= 4; off <<= 1) {   // coverage 7 lanes
                    const int o = __shfl_up_sync(0xffffffffu, F, off);
                    if (l >= off) F = max(F, o - DECAY * off);
                }
                const int Fnb = __shfl_up_sync(0xffffffffu, F, 1);
                const float sc = pow2f(E - F);
                L0 *= sc; L1 *= sc; L2 *= sc; L3 *= sc;
                b0 *= sc; b1 *= sc; b2 *= sc; b3 *= sc; b4 *= sc;
                E = F;
                scale_in = (l == 0) ? 0.f : pow2f(Fnb - F);
            }
        }
    } else {
        // ---------------- BACKWARD: frames 1023..512 -> beta_511 ----------------
        const float al1f = (y1 != y0) ? 1.f : 0.f;
        const float al2f = (y2 != y1) ? 1.f : 0.f;
        const float al3f = (y3 != y2) ? 1.f : 0.f;
        const int   ynx  = (l < 31) ? Y[4 * l + 4] : 0;           // label u=4(l+1)
        const float alnf = ((l < 31) && (ynx != y3)) ? 1.f : 0.f; // allow into next lane's L0

        #pragma unroll
        for (int g = 0; g < 3; ++g) {
            #pragma unroll
            for (int j = 0; j < 4; ++j) {
                const int f = 1023 - (g * 4 + j);
                cp_async16(rbase_sh + (uint32_t)(f & (RING - 1)) * (C_DIM * 4) + lane_off,
                           P + (size_t)f * C_DIM + l * 4);
            }
            cp_commit();
        }

        if (l == 31) { L3 = 1.f; b4 = 1.f; }   // beta_{1023}: states 255, 256
        E = (l == 31) ? 0 : SENT;

        #pragma unroll 1
        for (int k = 0; k < HALF_T / 4; ++k) {
            cp_wait2();
            __syncwarp();
            {
                const int i0 = 4 * k + 12;
                if (i0 < HALF_T) {
                    #pragma unroll
                    for (int j = 0; j < 4; ++j) {
                        const int f = 1023 - (i0 + j);
                        cp_async16(rbase_sh + (uint32_t)(f & (RING - 1)) * (C_DIM * 4) + lane_off,
                                   P + (size_t)f * C_DIM + l * 4);
                    }
                }
                cp_commit();
            }

            #pragma unroll
            for (int j = 0; j < 4; ++j) {
                const int f = 1023 - (4 * k + j);
                const float* row = ring[f & (RING - 1)];
                const float pbe = row[BLANK] + EPSV;
                const float p0 = row[y0] + EPSV;
                const float p1 = row[y1] + EPSV;
                const float p2 = row[y2] + EPSV;
                const float p3 = row[y3] + EPSV;
                const float pyn = row[ynx] + EPSV;

                // previous-step beta b0/L0 from lane l+1 (lane31 gets garbage, masked)
                const float bn = __shfl_down_sync(0xffffffffu, b0, 1);
                const float Ln = __shfl_down_sync(0xffffffffu, L0, 1);

                const float gb0 = b0 * pbe, gb1 = b1 * pbe, gb2 = b2 * pbe, gb3 = b3 * pbe;
                const float gb4 = b4 * pbe;
                const float gL0 = L0 * p0, gL1 = L1 * p1, gL2 = L2 * p2, gL3 = L3 * p3;

                const float gbn = bn * scale_in * pbe;
                const float gLn = Ln * scale_in * pyn;
                const float tb  = (l == 31) ? gb4 : gbn;
                const float tL  = (l == 31) ? 0.f : alnf * gLn;

                const float nb0 = gb0 + gL0;
                const float nb1 = gb1 + gL1;
                const float nb2 = gb2 + gL2;
                const float nb3 = gb3 + gL3;
                const float nL0 = __fmaf_rn(al1f, gL1, gL0 + gb1);
                const float nL1 = __fmaf_rn(al2f, gL2, gL1 + gb2);
                const float nL2 = __fmaf_rn(al3f, gL3, gL2 + gb3);
                const float nL3 = gL3 + tb + tL;

                L0 = nL0; L1 = nL1; L2 = nL2; L3 = nL3;
                b0 = nb0; b1 = nb1; b2 = nb2; b3 = nb3; b4 = gb4;
            }

            // renorm every 4-step window (overflow-safety critical)
            {
                const float m = fmaxf(fmaxf(fmaxf(L0, L1), fmaxf(L2, L3)),
                                      fmaxf(fmaxf(b0, b1), fmaxf(b2, fmaxf(b3, b4))));
                int Ep = SENT;
                if (m > 0.f) Ep = E + ((__float_as_int(m) >> 23) & 255) - 127;
                int F = Ep;
                #pragma unroll
                for (int off = 1; off <= 4; off <<= 1) {   // coverage 7 lanes
                    const int o = __shfl_down_sync(0xffffffffu, F, off);
                    if (l + off < 32) F = max(F, o - DECAY * off);
                }
                const int Fnb = __shfl_down_sync(0xffffffffu, F, 1);
                const float sc = pow2f(E - F);
                L0 *= sc; L1 *= sc; L2 *= sc; L3 *= sc;
                b0 *= sc; b1 *= sc; b2 *= sc; b3 *= sc; b4 *= sc;
                E = F;
                scale_in = (l == 31) ? 0.f : pow2f(Fnb - F);
            }
        }
    }

    // Publish boundary state.
    float* dst = g_vals[dir][b][l];
    dst[0] = b0; dst[1] = b1; dst[2] = b2; dst[3] = b3;
    dst[4] = L0; dst[5] = L1; dst[6] = L2; dst[7] = L3;
    dst[8] = b4;
    g_exps[dir][b][l] = E;

    // Rendezvous: second arriver of the (fwd,bwd) pair combines.
    __threadfence();
    int old = 0;
    if (l == 0) old = atomicAdd(&g_done[b], 1);
    old = __shfl_sync(0xffffffffu, old, 0);
    if (old & 1) {
        __threadfence();   // acquire: partner's stores precede its (even) increment
        const float* a = g_vals[0][b][l];
        const float* c = g_vals[1][b][l];
        float s = 0.f;
        #pragma unroll
        for (int i = 0; i < 9; ++i) s += a[i] * c[i];
        int X = g_exps[0][b][l] + g_exps[1][b][l];
        if (!(s > 0.f)) { s = 0.f; X = SENT * 2; }

        int M = X;
        #pragma unroll
        for (int off = 16; off; off >>= 1)
            M = max(M, __shfl_xor_sync(0xffffffffu, M, off));

        float v = s * pow2f(X - M);
        #pragma unroll
        for (int off = 16; off; off >>= 1)
            v += __shfl_xor_sync(0xffffffffu, v, off);

        if (l == 0)
            out[b] = (float)(-((double)M * 0.6931471805599453 + log((double)v)));
    }
}

extern "C" void kernel_launch(void* const* d_in, const int* in_sizes, int n_in,
                              void* d_out, int out_size)
{
    const int*   y_true = (const int*)d_in[0];
    const float* y_pred = (const float*)d_in[1];
    float*       out    = (float*)d_out;
    ctc_fused_kernel<<<2 * B_DIM, 32>>>(y_true, y_pred, out);
}

// round 10
// speedup vs baseline: 9.6861x; 1.0088x over previous
#include <cuda_runtime.h>
#include <cstdint>
#include <math.h>

// CTC forward loss via exact forward/backward split at T/2, fused combine.
// B=256, T=1024, C=128, U=128, S=257, blank=127.
// d_in[0]=y_true (int32 B*128), d_in[1]=y_pred (fp32 B*T*C). out: (B) fp32.
//
// Grid 512: even blocks forward (frames 0..511), odd blocks backward
// (frames 1023..512). One warp each; lane l owns labels/blanks u=4l..4l+3
// (lane 31 also blank u=128). Linear domain, per-lane block float:
// renorm every 4 steps (imported mass crosses at most one lane boundary per
// window -> no overflow), decayed prefix-max base agreement (DECAY=96,
// 3-shfl scan, coverage 7). Probability gathers for window k+1 are batched
// and double-buffered against window k's compute (hides LDS latency+conflicts).
// Second finisher of each (fwd,bwd) pair combines via atomic rendezvous.

#define T_DIM  1024
#define HALF_T 512
#define C_DIM  128
#define BLANK  127
#define EPSV   1e-7f
#define RING   16
#define SENT   (-(1 << 28))
#define DECAY  96
#define B_DIM  256

__device__ float g_vals[2][B_DIM][32][9];
__device__ int   g_exps[2][B_DIM][32];
__device__ int   g_done[B_DIM];   // zero-init; +2 per batch per launch (parity)

__device__ __forceinline__ uint32_t smem_u32(const void* p) {
    uint32_t a;
    asm("{ .reg .u64 t; cvta.to.shared.u64 t, %1; cvt.u32.u64 %0, t; }" : "=r"(a) : "l"(p));
    return a;
}
__device__ __forceinline__ void cp_async16(uint32_t dst, const void* src) {
    asm volatile("cp.async.cg.shared.global [%0], [%1], 16;" :: "r"(dst), "l"(src));
}
__device__ __forceinline__ void cp_commit() {
    asm volatile("cp.async.commit_group;" ::: "memory");
}
__device__ __forceinline__ void cp_wait2() {
    asm volatile("cp.async.wait_group 2;" ::: "memory");
}
__device__ __forceinline__ float pow2f(int d) {   // exact 2^d; d<=-127 -> 0
    d = min(d, 127);
    return (d <= -127) ? 0.f : __int_as_float((d + 127) << 23);
}

__global__ void __launch_bounds__(32)
ctc_fused_kernel(const int* __restrict__ y_true,
                 const float* __restrict__ y_pred,
                 float* __restrict__ out)
{
    __shared__ float ring[RING][C_DIM];

    const int b   = blockIdx.x >> 1;
    const int dir = blockIdx.x & 1;
    const int l   = threadIdx.x;
    const float* __restrict__ P = y_pred + (size_t)b * T_DIM * C_DIM;
    const int*   __restrict__ Y = y_true + (size_t)b * 128;

    const int y0 = Y[4 * l + 0];
    const int y1 = Y[4 * l + 1];
    const int y2 = Y[4 * l + 2];
    const int y3 = Y[4 * l + 3];

    const uint32_t rbase_sh = smem_u32(ring);
    const uint32_t lane_off = l * 16;

    float b0 = 0.f, b1 = 0.f, b2 = 0.f, b3 = 0.f, b4 = 0.f;
    float L0 = 0.f, L1 = 0.f, L2 = 0.f, L3 = 0.f;
    int   E;
    float scale_in = 0.f;
    const float is31 = (l == 31) ? 1.f : 0.f;

    if (dir == 0) {
        // ================= FORWARD: frames 0..511 -> alpha_511 =================
        const int yprev = (l == 0) ? -1 : Y[4 * l - 1];
        const float al0f = ((l > 0) && (y0 != yprev)) ? 1.f : 0.f;
        const float al1f = (y1 != y0) ? 1.f : 0.f;
        const float al2f = (y2 != y1) ? 1.f : 0.f;
        const float al3f = (y3 != y2) ? 1.f : 0.f;

        // Virtual init: running the t=0 step on (b0=1 @ lane0, rest 0) yields alpha_0.
        if (l == 0) b0 = 1.f;
        E = (l == 0) ? 0 : SENT;

        // prefetch windows 0..2
        #pragma unroll
        for (int g = 0; g < 3; ++g) {
            #pragma unroll
            for (int j = 0; j < 4; ++j) {
                const int r = g * 4 + j;
                cp_async16(rbase_sh + (uint32_t)(r & (RING - 1)) * (C_DIM * 4) + lane_off,
                           P + (size_t)r * C_DIM + l * 4);
            }
            cp_commit();
        }

        float Aqb[4], Aq0[4], Aq1[4], Aq2[4], Aq3[4];
        float Bqb[4], Bq0[4], Bq1[4], Bq2[4], Bq3[4];

        auto gatherF = [&](int kk, float (&qb)[4], float (&q0)[4], float (&q1)[4],
                           float (&q2)[4], float (&q3)[4]) {
            #pragma unroll
            for (int j = 0; j < 4; ++j) {
                const float* r = ring[(4 * kk + j) & (RING - 1)];
                qb[j] = r[BLANK] + EPSV;
                q0[j] = r[y0] + EPSV;
                q1[j] = r[y1] + EPSV;
                q2[j] = r[y2] + EPSV;
                q3[j] = r[y3] + EPSV;
            }
        };
        auto stepF = [&](const float (&qb)[4], const float (&q0)[4], const float (&q1)[4],
                         const float (&q2)[4], const float (&q3)[4]) {
            #pragma unroll
            for (int j = 0; j < 4; ++j) {
                const float ap = __shfl_up_sync(0xffffffffu, L3, 1) * scale_in;
                const float nL0 = __fmaf_rn(al0f, ap, L0 + b0) * q0[j];
                const float nL1 = __fmaf_rn(al1f, L0, L1 + b1) * q1[j];
                const float nL2 = __fmaf_rn(al2f, L1, L2 + b2) * q2[j];
                const float nL3 = __fmaf_rn(al3f, L2, L3 + b3) * q3[j];
                const float nb0 = (b0 + ap) * qb[j];
                const float nb1 = (b1 + L0) * qb[j];
                const float nb2 = (b2 + L1) * qb[j];
                const float nb3 = (b3 + L2) * qb[j];
                const float nb4 = __fmaf_rn(is31, L3, b4) * qb[j];
                L0 = nL0; L1 = nL1; L2 = nL2; L3 = nL3;
                b0 = nb0; b1 = nb1; b2 = nb2; b3 = nb3; b4 = nb4;
            }
        };
        auto renormF = [&]() {
            const float m = fmaxf(fmaxf(fmaxf(L0, L1), fmaxf(L2, L3)),
                                  fmaxf(fmaxf(b0, b1), fmaxf(b2, fmaxf(b3, b4))));
            int Ep = SENT;
            if (m > 0.f) Ep = E + ((__float_as_int(m) >> 23) & 255) - 127;
            int F = Ep;
            #pragma unroll
            for (int off = 1; off <= 4; off <<= 1) {
                const int o = __shfl_up_sync(0xffffffffu, F, off);
                if (l >= off) F = max(F, o - DECAY * off);
            }
            const int Fnb = __shfl_up_sync(0xffffffffu, F, 1);
            const float sc = pow2f(E - F);
            L0 *= sc; L1 *= sc; L2 *= sc; L3 *= sc;
            b0 *= sc; b1 *= sc; b2 *= sc; b3 *= sc; b4 *= sc;
            E = F;
            scale_in = (l == 0) ? 0.f : pow2f(Fnb - F);
        };
        auto issueF = [&](int kk) {   // prefetch window kk (commit even if empty)
            const int r0 = 4 * kk;
            if (r0 < HALF_T) {
                #pragma unroll
                for (int j = 0; j < 4; ++j) {
                    const int r = r0 + j;
                    cp_async16(rbase_sh + (uint32_t)(r & (RING - 1)) * (C_DIM * 4) + lane_off,
                               P + (size_t)r * C_DIM + l * 4);
                }
            }
            cp_commit();
        };

        cp_wait2(); __syncwarp();
        gatherF(0, Aqb, Aq0, Aq1, Aq2, Aq3);

        #pragma unroll 1
        for (int k2 = 0; k2 < 64; ++k2) {
            {   const int k = 2 * k2;
                issueF(k + 3);
                cp_wait2(); __syncwarp();
                gatherF(k + 1, Bqb, Bq0, Bq1, Bq2, Bq3);
                stepF(Aqb, Aq0, Aq1, Aq2, Aq3);
                renormF();
            }
            {   const int k = 2 * k2 + 1;
                issueF(k + 3);
                cp_wait2(); __syncwarp();
                if (k2 < 63) gatherF(k + 1, Aqb, Aq0, Aq1, Aq2, Aq3);
                stepF(Bqb, Bq0, Bq1, Bq2, Bq3);
                renormF();
            }
        }
    } else {
        // ================= BACKWARD: frames 1023..512 -> beta_511 =================
        const float al1f = (y1 != y0) ? 1.f : 0.f;
        const float al2f = (y2 != y1) ? 1.f : 0.f;
        const float al3f = (y3 != y2) ? 1.f : 0.f;
        const int   ynx  = (l < 31) ? Y[4 * l + 4] : 0;
        const float alnf = ((l < 31) && (ynx != y3)) ? 1.f : 0.f;

        if (l == 31) { L3 = 1.f; b4 = 1.f; }
        E = (l == 31) ? 0 : SENT;

        #pragma unroll
        for (int g = 0; g < 3; ++g) {
            #pragma unroll
            for (int j = 0; j < 4; ++j) {
                const int f = 1023 - (g * 4 + j);
                cp_async16(rbase_sh + (uint32_t)(f & (RING - 1)) * (C_DIM * 4) + lane_off,
                           P + (size_t)f * C_DIM + l * 4);
            }
            cp_commit();
        }

        float Aqb[4], Aq0[4], Aq1[4], Aq2[4], Aq3[4], Aqn[4];
        float Bqb[4], Bq0[4], Bq1[4], Bq2[4], Bq3[4], Bqn[4];

        auto gatherB = [&](int kk, float (&qb)[4], float (&q0)[4], float (&q1)[4],
                           float (&q2)[4], float (&q3)[4], float (&qn)[4]) {
            #pragma unroll
            for (int j = 0; j < 4; ++j) {
                const float* r = ring[(1023 - (4 * kk + j)) & (RING - 1)];
                qb[j] = r[BLANK] + EPSV;
                q0[j] = r[y0] + EPSV;
                q1[j] = r[y1] + EPSV;
                q2[j] = r[y2] + EPSV;
                q3[j] = r[y3] + EPSV;
                qn[j] = r[ynx] + EPSV;
            }
        };
        auto stepB = [&](const float (&qb)[4], const float (&q0)[4], const float (&q1)[4],
                         const float (&q2)[4], const float (&q3)[4], const float (&qn)[4]) {
            #pragma unroll
            for (int j = 0; j < 4; ++j) {
                // hoisted: shfl result feeds exactly one multiply then one FMA
                const float sqb = scale_in * qb[j];
                const float sqn = scale_in * qn[j];
                const float bn = __shfl_down_sync(0xffffffffu, b0, 1);
                const float Ln = __shfl_down_sync(0xffffffffu, L0, 1);

                const float gb0 = b0 * qb[j], gb1 = b1 * qb[j];
                const float gb2 = b2 * qb[j], gb3 = b3 * qb[j];
                const float gb4 = b4 * qb[j];
                const float gL0 = L0 * q0[j], gL1 = L1 * q1[j];
                const float gL2 = L2 * q2[j], gL3 = L3 * q3[j];
                // scale_in==0 on lane31 -> imported terms vanish there; gb4==0 off lane31
                const float gbn = bn * sqb;
                const float gLn = Ln * sqn;

                const float nb0 = gb0 + gL0;
                const float nb1 = gb1 + gL1;
                const float nb2 = gb2 + gL2;
                const float nb3 = gb3 + gL3;
                const float nL0 = __fmaf_rn(al1f, gL1, gL0 + gb1);
                const float nL1 = __fmaf_rn(al2f, gL2, gL1 + gb2);
                const float nL2 = __fmaf_rn(al3f, gL3, gL2 + gb3);
                const float nL3 = __fmaf_rn(alnf, gLn, gL3 + gbn + gb4);

                L0 = nL0; L1 = nL1; L2 = nL2; L3 = nL3;
                b0 = nb0; b1 = nb1; b2 = nb2; b3 = nb3; b4 = gb4;
            }
        };
        auto renormB = [&]() {
            const float m = fmaxf(fmaxf(fmaxf(L0, L1), fmaxf(L2, L3)),
                                  fmaxf(fmaxf(b0, b1), fmaxf(b2, fmaxf(b3, b4))));
            int Ep = SENT;
            if (m > 0.f) Ep = E + ((__float_as_int(m) >> 23) & 255) - 127;
            int F = Ep;
            #pragma unroll
            for (int off = 1; off <= 4; off <<= 1) {
                const int o = __shfl_down_sync(0xffffffffu, F, off);
                if (l + off < 32) F = max(F, o - DECAY * off);
            }
            const int Fnb = __shfl_down_sync(0xffffffffu, F, 1);
            const float sc = pow2f(E - F);
            L0 *= sc; L1 *= sc; L2 *= sc; L3 *= sc;
            b0 *= sc; b1 *= sc; b2 *= sc; b3 *= sc; b4 *= sc;
            E = F;
            scale_in = (l == 31) ? 0.f : pow2f(Fnb - F);
        };
        auto issueB = [&](int kk) {
            const int i0 = 4 * kk;
            if (i0 < HALF_T) {
                #pragma unroll
                for (int j = 0; j < 4; ++j) {
                    const int f = 1023 - (i0 + j);
                    cp_async16(rbase_sh + (uint32_t)(f & (RING - 1)) * (C_DIM * 4) + lane_off,
                               P + (size_t)f * C_DIM + l * 4);
                }
            }
            cp_commit();
        };

        cp_wait2(); __syncwarp();
        gatherB(0, Aqb, Aq0, Aq1, Aq2, Aq3, Aqn);

        #pragma unroll 1
        for (int k2 = 0; k2 < 64; ++k2) {
            {   const int k = 2 * k2;
                issueB(k + 3);
                cp_wait2(); __syncwarp();
                gatherB(k + 1, Bqb, Bq0, Bq1, Bq2, Bq3, Bqn);
                stepB(Aqb, Aq0, Aq1, Aq2, Aq3, Aqn);
                renormB();
            }
            {   const int k = 2 * k2 + 1;
                issueB(k + 3);
                cp_wait2(); __syncwarp();
                if (k2 < 63) gatherB(k + 1, Aqb, Aq0, Aq1, Aq2, Aq3, Aqn);
                stepB(Bqb, Bq0, Bq1, Bq2, Bq3, Bqn);
                renormB();
            }
        }
    }

    // Publish boundary state.
    float* dst = g_vals[dir][b][l];
    dst[0] = b0; dst[1] = b1; dst[2] = b2; dst[3] = b3;
    dst[4] = L0; dst[5] = L1; dst[6] = L2; dst[7] = L3;
    dst[8] = b4;
    g_exps[dir][b][l] = E;

    // Rendezvous: second arriver of the (fwd,bwd) pair combines.
    __threadfence();
    int old = 0;
    if (l == 0) old = atomicAdd(&g_done[b], 1);
    old = __shfl_sync(0xffffffffu, old, 0);
    if (old & 1) {
        __threadfence();   // acquire: partner's stores precede its increment
        const float* a = g_vals[0][b][l];
        const float* c = g_vals[1][b][l];
        float s = 0.f;
        #pragma unroll
        for (int i = 0; i < 9; ++i) s += a[i] * c[i];
        int X = g_exps[0][b][l] + g_exps[1][b][l];
        if (!(s > 0.f)) { s = 0.f; X = SENT * 2; }

        int M = X;
        #pragma unroll
        for (int off = 16; off; off >>= 1)
            M = max(M, __shfl_xor_sync(0xffffffffu, M, off));

        float v = s * pow2f(X - M);
        #pragma unroll
        for (int off = 16; off; off >>= 1)
            v += __shfl_xor_sync(0xffffffffu, v, off);

        if (l == 0)
            out[b] = (float)(-((double)M * 0.6931471805599453 + log((double)v)));
    }
}

extern "C" void kernel_launch(void* const* d_in, const int* in_sizes, int n_in,
                              void* d_out, int out_size)
{
    const int*   y_true = (const int*)d_in[0];
    const float* y_pred = (const float*)d_in[1];
    float*       out    = (float*)d_out;
    ctc_fused_kernel<<<2 * B_DIM, 32>>>(y_true, y_pred, out);
}

// round 11
// speedup vs baseline: 9.9770x; 1.0300x over previous
#include <cuda_runtime.h>
#include <cstdint>
#include <math.h>

// CTC forward loss via exact forward/backward split at T/2, fused combine.
// B=256, T=1024, C=128, U=128, S=257, blank=127.
// d_in[0]=y_true (int32 B*128), d_in[1]=y_pred (fp32 B*T*C). out: (B) fp32.
//
// Grid 128, block 128 (4 warps). Warp w handles batch 2*blockIdx+(w>>1),
// direction w&1 (0=forward frames 0..511, 1=backward frames 1023..512).
// Four warps -> SMSPs 0..3 via wid%4: full scheduler coverage (a 1-warp block
// puts every warp on SMSP 0 and serializes the SM 3.5-deep -- the R10 bug).
// Lane l owns labels/blanks u=4l..4l+3 (lane 31 also blank u=128). Linear
// domain, per-lane block float: renorm every 4 steps (imported mass crosses at
// most one lane boundary per window -> no overflow), decayed prefix-max base
// agreement (DECAY=96, 3-shfl scan). Per-warp cp.async ring, 3 windows deep.
// Pairs combine in-block through shared staging after __syncthreads.

#define T_DIM  1024
#define HALF_T 512
#define C_DIM  128
#define BLANK  127
#define EPSV   1e-7f
#define RING   16
#define SENT   (-(1 << 28))
#define DECAY  96
#define B_DIM  256

__device__ __forceinline__ uint32_t smem_u32(const void* p) {
    uint32_t a;
    asm("{ .reg .u64 t; cvta.to.shared.u64 t, %1; cvt.u32.u64 %0, t; }" : "=r"(a) : "l"(p));
    return a;
}
__device__ __forceinline__ void cp_async16(uint32_t dst, const void* src) {
    asm volatile("cp.async.cg.shared.global [%0], [%1], 16;" :: "r"(dst), "l"(src));
}
__device__ __forceinline__ void cp_commit() {
    asm volatile("cp.async.commit_group;" ::: "memory");
}
__device__ __forceinline__ void cp_wait2() {
    asm volatile("cp.async.wait_group 2;" ::: "memory");
}
__device__ __forceinline__ float pow2f(int d) {   // exact 2^d; d<=-127 -> 0
    d = min(d, 127);
    return (d <= -127) ? 0.f : __int_as_float((d + 127) << 23);
}

__global__ void __launch_bounds__(128)
ctc_fused_kernel(const int* __restrict__ y_true,
                 const float* __restrict__ y_pred,
                 float* __restrict__ out)
{
    __shared__ float ring4[4][RING][C_DIM];   // 32 KB, one ring per warp
    __shared__ float s_vals[4][32][9];        // staging for combine
    __shared__ int   s_exps[4][32];

    const int tid = threadIdx.x;
    const int wid = tid >> 5;
    const int l   = tid & 31;
    const int b   = blockIdx.x * 2 + (wid >> 1);
    const int dir = wid & 1;

    const float* __restrict__ P = y_pred + (size_t)b * T_DIM * C_DIM;
    const int*   __restrict__ Y = y_true + (size_t)b * 128;

    const int y0 = Y[4 * l + 0];
    const int y1 = Y[4 * l + 1];
    const int y2 = Y[4 * l + 2];
    const int y3 = Y[4 * l + 3];

    float (*ring)[C_DIM] = ring4[wid];
    const uint32_t rbase_sh = smem_u32(ring);
    const uint32_t lane_off = l * 16;

    float b0 = 0.f, b1 = 0.f, b2 = 0.f, b3 = 0.f, b4 = 0.f;
    float L0 = 0.f, L1 = 0.f, L2 = 0.f, L3 = 0.f;
    int   E;
    float scale_in = 0.f;
    const float is31 = (l == 31) ? 1.f : 0.f;

    if (dir == 0) {
        // ================= FORWARD: frames 0..511 -> alpha_511 =================
        const int yprev = (l == 0) ? -1 : Y[4 * l - 1];
        const float al0f = ((l > 0) && (y0 != yprev)) ? 1.f : 0.f;
        const float al1f = (y1 != y0) ? 1.f : 0.f;
        const float al2f = (y2 != y1) ? 1.f : 0.f;
        const float al3f = (y3 != y2) ? 1.f : 0.f;

        // Virtual init: the t=0 step on (b0=1 @ lane0, rest 0) yields alpha_0.
        if (l == 0) b0 = 1.f;
        E = (l == 0) ? 0 : SENT;

        #pragma unroll
        for (int g = 0; g < 3; ++g) {
            #pragma unroll
            for (int j = 0; j < 4; ++j) {
                const int r = g * 4 + j;
                cp_async16(rbase_sh + (uint32_t)(r & (RING - 1)) * (C_DIM * 4) + lane_off,
                           P + (size_t)r * C_DIM + l * 4);
            }
            cp_commit();
        }

        float Aqb[4], Aq0[4], Aq1[4], Aq2[4], Aq3[4];
        float Bqb[4], Bq0[4], Bq1[4], Bq2[4], Bq3[4];

        auto gatherF = [&](int kk, float (&qb)[4], float (&q0)[4], float (&q1)[4],
                           float (&q2)[4], float (&q3)[4]) {
            #pragma unroll
            for (int j = 0; j < 4; ++j) {
                const float* r = ring[(4 * kk + j) & (RING - 1)];
                qb[j] = r[BLANK] + EPSV;
                q0[j] = r[y0] + EPSV;
                q1[j] = r[y1] + EPSV;
                q2[j] = r[y2] + EPSV;
                q3[j] = r[y3] + EPSV;
            }
        };
        auto stepF = [&](const float (&qb)[4], const float (&q0)[4], const float (&q1)[4],
                         const float (&q2)[4], const float (&q3)[4]) {
            #pragma unroll
            for (int j = 0; j < 4; ++j) {
                const float ap = __shfl_up_sync(0xffffffffu, L3, 1) * scale_in;
                const float nL0 = __fmaf_rn(al0f, ap, L0 + b0) * q0[j];
                const float nL1 = __fmaf_rn(al1f, L0, L1 + b1) * q1[j];
                const float nL2 = __fmaf_rn(al2f, L1, L2 + b2) * q2[j];
                const float nL3 = __fmaf_rn(al3f, L2, L3 + b3) * q3[j];
                const float nb0 = (b0 + ap) * qb[j];
                const float nb1 = (b1 + L0) * qb[j];
                const float nb2 = (b2 + L1) * qb[j];
                const float nb3 = (b3 + L2) * qb[j];
                const float nb4 = __fmaf_rn(is31, L3, b4) * qb[j];
                L0 = nL0; L1 = nL1; L2 = nL2; L3 = nL3;
                b0 = nb0; b1 = nb1; b2 = nb2; b3 = nb3; b4 = nb4;
            }
        };
        auto renormF = [&]() {
            const float m = fmaxf(fmaxf(fmaxf(L0, L1), fmaxf(L2, L3)),
                                  fmaxf(fmaxf(b0, b1), fmaxf(b2, fmaxf(b3, b4))));
            int Ep = SENT;
            if (m > 0.f) Ep = E + ((__float_as_int(m) >> 23) & 255) - 127;
            int F = Ep;
            #pragma unroll
            for (int off = 1; off <= 4; off <<= 1) {
                const int o = __shfl_up_sync(0xffffffffu, F, off);
                if (l >= off) F = max(F, o - DECAY * off);
            }
            const int Fnb = __shfl_up_sync(0xffffffffu, F, 1);
            const float sc = pow2f(E - F);
            L0 *= sc; L1 *= sc; L2 *= sc; L3 *= sc;
            b0 *= sc; b1 *= sc; b2 *= sc; b3 *= sc; b4 *= sc;
            E = F;
            scale_in = (l == 0) ? 0.f : pow2f(Fnb - F);
        };
        auto issueF = [&](int kk) {
            const int r0 = 4 * kk;
            if (r0 < HALF_T) {
                #pragma unroll
                for (int j = 0; j < 4; ++j) {
                    const int r = r0 + j;
                    cp_async16(rbase_sh + (uint32_t)(r & (RING - 1)) * (C_DIM * 4) + lane_off,
                               P + (size_t)r * C_DIM + l * 4);
                }
            }
            cp_commit();
        };

        cp_wait2(); __syncwarp();
        gatherF(0, Aqb, Aq0, Aq1, Aq2, Aq3);

        #pragma unroll 1
        for (int k2 = 0; k2 < 64; ++k2) {
            {   const int k = 2 * k2;
                issueF(k + 3);
                cp_wait2(); __syncwarp();
                gatherF(k + 1, Bqb, Bq0, Bq1, Bq2, Bq3);
                stepF(Aqb, Aq0, Aq1, Aq2, Aq3);
                renormF();
            }
            {   const int k = 2 * k2 + 1;
                issueF(k + 3);
                cp_wait2(); __syncwarp();
                if (k2 < 63) gatherF(k + 1, Aqb, Aq0, Aq1, Aq2, Aq3);
                stepF(Bqb, Bq0, Bq1, Bq2, Bq3);
                renormF();
            }
        }
    } else {
        // ================= BACKWARD: frames 1023..512 -> beta_511 =================
        const float al1f = (y1 != y0) ? 1.f : 0.f;
        const float al2f = (y2 != y1) ? 1.f : 0.f;
        const float al3f = (y3 != y2) ? 1.f : 0.f;
        const int   ynx  = (l < 31) ? Y[4 * l + 4] : 0;
        const float alnf = ((l < 31) && (ynx != y3)) ? 1.f : 0.f;

        if (l == 31) { L3 = 1.f; b4 = 1.f; }
        E = (l == 31) ? 0 : SENT;

        #pragma unroll
        for (int g = 0; g < 3; ++g) {
            #pragma unroll
            for (int j = 0; j < 4; ++j) {
                const int f = 1023 - (g * 4 + j);
                cp_async16(rbase_sh + (uint32_t)(f & (RING - 1)) * (C_DIM * 4) + lane_off,
                           P + (size_t)f * C_DIM + l * 4);
            }
            cp_commit();
        }

        float Aqb[4], Aq0[4], Aq1[4], Aq2[4], Aq3[4], Aqn[4];
        float Bqb[4], Bq0[4], Bq1[4], Bq2[4], Bq3[4], Bqn[4];

        auto gatherB = [&](int kk, float (&qb)[4], float (&q0)[4], float (&q1)[4],
                           float (&q2)[4], float (&q3)[4], float (&qn)[4]) {
            #pragma unroll
            for (int j = 0; j < 4; ++j) {
                const float* r = ring[(1023 - (4 * kk + j)) & (RING - 1)];
                qb[j] = r[BLANK] + EPSV;
                q0[j] = r[y0] + EPSV;
                q1[j] = r[y1] + EPSV;
                q2[j] = r[y2] + EPSV;
                q3[j] = r[y3] + EPSV;
                qn[j] = r[ynx] + EPSV;
            }
        };
        auto stepB = [&](const float (&qb)[4], const float (&q0)[4], const float (&q1)[4],
                         const float (&q2)[4], const float (&q3)[4], const float (&qn)[4]) {
            #pragma unroll
            for (int j = 0; j < 4; ++j) {
                const float sqb = scale_in * qb[j];
                const float sqn = scale_in * qn[j];
                const float bn = __shfl_down_sync(0xffffffffu, b0, 1);
                const float Ln = __shfl_down_sync(0xffffffffu, L0, 1);

                const float gb0 = b0 * qb[j], gb1 = b1 * qb[j];
                const float gb2 = b2 * qb[j], gb3 = b3 * qb[j];
                const float gb4 = b4 * qb[j];
                const float gL0 = L0 * q0[j], gL1 = L1 * q1[j];
                const float gL2 = L2 * q2[j], gL3 = L3 * q3[j];
                const float gbn = bn * sqb;   // lane31: scale_in==0 -> vanishes
                const float gLn = Ln * sqn;

                const float nb0 = gb0 + gL0;
                const float nb1 = gb1 + gL1;
                const float nb2 = gb2 + gL2;
                const float nb3 = gb3 + gL3;
                const float nL0 = __fmaf_rn(al1f, gL1, gL0 + gb1);
                const float nL1 = __fmaf_rn(al2f, gL2, gL1 + gb2);
                const float nL2 = __fmaf_rn(al3f, gL3, gL2 + gb3);
                const float nL3 = __fmaf_rn(alnf, gLn, gL3 + gbn + gb4);

                L0 = nL0; L1 = nL1; L2 = nL2; L3 = nL3;
                b0 = nb0; b1 = nb1; b2 = nb2; b3 = nb3; b4 = gb4;
            }
        };
        auto renormB = [&]() {
            const float m = fmaxf(fmaxf(fmaxf(L0, L1), fmaxf(L2, L3)),
                                  fmaxf(fmaxf(b0, b1), fmaxf(b2, fmaxf(b3, b4))));
            int Ep = SENT;
            if (m > 0.f) Ep = E + ((__float_as_int(m) >> 23) & 255) - 127;
            int F = Ep;
            #pragma unroll
            for (int off = 1; off <= 4; off <<= 1) {
                const int o = __shfl_down_sync(0xffffffffu, F, off);
                if (l + off < 32) F = max(F, o - DECAY * off);
            }
            const int Fnb = __shfl_down_sync(0xffffffffu, F, 1);
            const float sc = pow2f(E - F);
            L0 *= sc; L1 *= sc; L2 *= sc; L3 *= sc;
            b0 *= sc; b1 *= sc; b2 *= sc; b3 *= sc; b4 *= sc;
            E = F;
            scale_in = (l == 31) ? 0.f : pow2f(Fnb - F);
        };
        auto issueB = [&](int kk) {
            const int i0 = 4 * kk;
            if (i0 < HALF_T) {
                #pragma unroll
                for (int j = 0; j < 4; ++j) {
                    const int f = 1023 - (i0 + j);
                    cp_async16(rbase_sh + (uint32_t)(f & (RING - 1)) * (C_DIM * 4) + lane_off,
                               P + (size_t)f * C_DIM + l * 4);
                }
            }
            cp_commit();
        };

        cp_wait2(); __syncwarp();
        gatherB(0, Aqb, Aq0, Aq1, Aq2, Aq3, Aqn);

        #pragma unroll 1
        for (int k2 = 0; k2 < 64; ++k2) {
            {   const int k = 2 * k2;
                issueB(k + 3);
                cp_wait2(); __syncwarp();
                gatherB(k + 1, Bqb, Bq0, Bq1, Bq2, Bq3, Bqn);
                stepB(Aqb, Aq0, Aq1, Aq2, Aq3, Aqn);
                renormB();
            }
            {   const int k = 2 * k2 + 1;
                issueB(k + 3);
                cp_wait2(); __syncwarp();
                if (k2 < 63) gatherB(k + 1, Aqb, Aq0, Aq1, Aq2, Aq3, Aqn);
                stepB(Bqb, Bq0, Bq1, Bq2, Bq3, Bqn);
                renormB();
            }
        }
    }

    // Publish boundary state to shared staging.
    float* dst = s_vals[wid][l];
    dst[0] = b0; dst[1] = b1; dst[2] = b2; dst[3] = b3;
    dst[4] = L0; dst[5] = L1; dst[6] = L2; dst[7] = L3;
    dst[8] = b4;
    s_exps[wid][l] = E;

    __syncthreads();

    // Warps 0 and 2 combine their (fwd,bwd) pair: ll = sum_s alpha*beta.
    if ((wid & 1) == 0) {
        const float* a = s_vals[wid][l];
        const float* c = s_vals[wid + 1][l];
        float s = 0.f;
        #pragma unroll
        for (int i = 0; i < 9; ++i) s += a[i] * c[i];
        int X = s_exps[wid][l] + s_exps[wid + 1][l];
        if (!(s > 0.f)) { s = 0.f; X = SENT * 2; }

        int M = X;
        #pragma unroll
        for (int off = 16; off; off >>= 1)
            M = max(M, __shfl_xor_sync(0xffffffffu, M, off));

        float v = s * pow2f(X - M);
        #pragma unroll
        for (int off = 16; off; off >>= 1)
            v += __shfl_xor_sync(0xffffffffu, v, off);

        if (l == 0)
            out[b] = (float)(-((double)M * 0.6931471805599453 + log((double)v)));
    }
}

extern "C" void kernel_launch(void* const* d_in, const int* in_sizes, int n_in,
                              void* d_out, int out_size)
{
    const int*   y_true = (const int*)d_in[0];
    const float* y_pred = (const float*)d_in[1];
    float*       out    = (float*)d_out;
    ctc_fused_kernel<<<B_DIM / 2, 128>>>(y_true, y_pred, out);
}

// round 13
// speedup vs baseline: 10.1326x; 1.0156x over previous
#include <cuda_runtime.h>
#include <cstdint>
#include <math.h>

// CTC forward loss via exact forward/backward split at T/2, fused combine.
// B=256, T=1024, C=128, U=128, S=257, blank=127.
// d_in[0]=y_true (int32 B*128), d_in[1]=y_pred (fp32 B*T*C). out: (B) fp32.
//
// Grid 128, block 128 (4 warps): warp w -> batch 2*blockIdx+(w>>1), dir w&1.
// Lane l owns labels/blanks u=4l..4l+3 (lane 31 also blank u=128).
// Linear domain, per-lane block float. Renorm every EIGHT steps with
// DECAY=48/lane-hop: import <=2^48 rel, growth <=2^13, at most two lane
// crossings per window -> <=2^109 < 2^127 (the R5 inf was DECAY=96 @ 8 steps
// -> 2^192). Scan F_l = max(Ep_l, Ep_{l-1}-48, Ep_{l-2}-96, Ep_{l-3}-144)
// via 2 shfls gives Lipschitz F_{l-1}-F_l <= 48 on all mass-relevant paths.
// Backward qn comes from shfl_down of q0 (ynx == neighbor's y0).
// Pairs combine in-block through shared staging after __syncthreads.

#define T_DIM  1024
#define HALF_T 512
#define C_DIM  128
#define BLANK  127
#define EPSV   1e-7f
#define RING   16
#define SENT   (-(1 << 28))
#define DECAY  48
#define B_DIM  256

__device__ __forceinline__ uint32_t smem_u32(const void* p) {
    uint32_t a;
    asm("{ .reg .u64 t; cvta.to.shared.u64 t, %1; cvt.u32.u64 %0, t; }" : "=r"(a) : "l"(p));
    return a;
}
__device__ __forceinline__ void cp_async16(uint32_t dst, const void* src) {
    asm volatile("cp.async.cg.shared.global [%0], [%1], 16;" :: "r"(dst), "l"(src));
}
__device__ __forceinline__ void cp_commit() {
    asm volatile("cp.async.commit_group;" ::: "memory");
}
__device__ __forceinline__ void cp_wait2() {
    asm volatile("cp.async.wait_group 2;" ::: "memory");
}
__device__ __forceinline__ float pow2f(int d) {   // exact 2^d; d<=-127 -> 0, clamp +127
    d = min(d, 127);
    return (d <= -127) ? 0.f : __int_as_float((d + 127) << 23);
}

__global__ void __launch_bounds__(128)
ctc_fused_kernel(const int* __restrict__ y_true,
                 const float* __restrict__ y_pred,
                 float* __restrict__ out)
{
    __shared__ float ring4[4][RING][C_DIM];   // 32 KB, one ring per warp
    __shared__ float s_vals[4][32][9];
    __shared__ int   s_exps[4][32];

    const int tid = threadIdx.x;
    const int wid = tid >> 5;
    const int l   = tid & 31;
    const int b   = blockIdx.x * 2 + (wid >> 1);
    const int dir = wid & 1;

    const float* __restrict__ P = y_pred + (size_t)b * T_DIM * C_DIM;
    const int*   __restrict__ Y = y_true + (size_t)b * 128;

    const int y0 = Y[4 * l + 0];
    const int y1 = Y[4 * l + 1];
    const int y2 = Y[4 * l + 2];
    const int y3 = Y[4 * l + 3];

    float (*ring)[C_DIM] = ring4[wid];
    const uint32_t rbase_sh = smem_u32(ring);
    const uint32_t lane_off = l * 16;

    float b0 = 0.f, b1 = 0.f, b2 = 0.f, b3 = 0.f, b4 = 0.f;
    float L0 = 0.f, L1 = 0.f, L2 = 0.f, L3 = 0.f;
    int   E;
    float scale_in = 0.f;
    const float is31 = (l == 31) ? 1.f : 0.f;

    if (dir == 0) {
        // ================= FORWARD: frames 0..511 -> alpha_511 =================
        const int yprev = (l == 0) ? -1 : Y[4 * l - 1];
        const float al0f = ((l > 0) && (y0 != yprev)) ? 1.f : 0.f;
        const float al1f = (y1 != y0) ? 1.f : 0.f;
        const float al2f = (y2 != y1) ? 1.f : 0.f;
        const float al3f = (y3 != y2) ? 1.f : 0.f;

        // Virtual init: the t=0 step on (b0=1 @ lane0, rest 0) yields alpha_0.
        if (l == 0) b0 = 1.f;
        E = (l == 0) ? 0 : SENT;

        #pragma unroll
        for (int g = 0; g < 3; ++g) {
            #pragma unroll
            for (int j = 0; j < 4; ++j) {
                const int r = g * 4 + j;
                cp_async16(rbase_sh + (uint32_t)(r & (RING - 1)) * (C_DIM * 4) + lane_off,
                           P + (size_t)r * C_DIM + l * 4);
            }
            cp_commit();
        }

        float Aqb[4], Aq0[4], Aq1[4], Aq2[4], Aq3[4];
        float Bqb[4], Bq0[4], Bq1[4], Bq2[4], Bq3[4];

        auto gatherF = [&](int kk, float (&qb)[4], float (&q0)[4], float (&q1)[4],
                           float (&q2)[4], float (&q3)[4]) {
            #pragma unroll
            for (int j = 0; j < 4; ++j) {
                const float* r = ring[(4 * kk + j) & (RING - 1)];
                qb[j] = r[BLANK] + EPSV;
                q0[j] = r[y0] + EPSV;
                q1[j] = r[y1] + EPSV;
                q2[j] = r[y2] + EPSV;
                q3[j] = r[y3] + EPSV;
            }
        };
        auto stepF = [&](const float (&qb)[4], const float (&q0)[4], const float (&q1)[4],
                         const float (&q2)[4], const float (&q3)[4]) {
            #pragma unroll
            for (int j = 0; j < 4; ++j) {
                const float ap = __shfl_up_sync(0xffffffffu, L3, 1) * scale_in;
                const float nL0 = __fmaf_rn(al0f, ap, L0 + b0) * q0[j];
                const float nL1 = __fmaf_rn(al1f, L0, L1 + b1) * q1[j];
                const float nL2 = __fmaf_rn(al2f, L1, L2 + b2) * q2[j];
                const float nL3 = __fmaf_rn(al3f, L2, L3 + b3) * q3[j];
                const float nb0 = (b0 + ap) * qb[j];
                const float nb1 = (b1 + L0) * qb[j];
                const float nb2 = (b2 + L1) * qb[j];
                const float nb3 = (b3 + L2) * qb[j];
                const float nb4 = __fmaf_rn(is31, L3, b4) * qb[j];
                L0 = nL0; L1 = nL1; L2 = nL2; L3 = nL3;
                b0 = nb0; b1 = nb1; b2 = nb2; b3 = nb3; b4 = nb4;
            }
        };
        auto renormF = [&]() {
            const float m = fmaxf(fmaxf(fmaxf(L0, L1), fmaxf(L2, L3)),
                                  fmaxf(fmaxf(b0, b1), fmaxf(b2, fmaxf(b3, b4))));
            int Ep = SENT;
            if (m > 0.f) Ep = E + ((__float_as_int(m) >> 23) & 255) - 127;
            const int t1 = __shfl_up_sync(0xffffffffu, Ep, 1);
            int F = (l >= 1) ? max(Ep, t1 - DECAY) : Ep;
            const int t2 = __shfl_up_sync(0xffffffffu, F, 2);
            if (l >= 2) F = max(F, t2 - 2 * DECAY);
            const int Fnb = __shfl_up_sync(0xffffffffu, F, 1);
            const float sc = pow2f(E - F);
            L0 *= sc; L1 *= sc; L2 *= sc; L3 *= sc;
            b0 *= sc; b1 *= sc; b2 *= sc; b3 *= sc; b4 *= sc;
            E = F;
            scale_in = (l == 0) ? 0.f : pow2f(Fnb - F);
        };
        auto issueF = [&](int kk) {
            const int r0 = 4 * kk;
            if (r0 < HALF_T) {
                #pragma unroll
                for (int j = 0; j < 4; ++j) {
                    const int r = r0 + j;
                    cp_async16(rbase_sh + (uint32_t)(r & (RING - 1)) * (C_DIM * 4) + lane_off,
                               P + (size_t)r * C_DIM + l * 4);
                }
            }
            cp_commit();
        };

        cp_wait2(); __syncwarp();
        gatherF(0, Aqb, Aq0, Aq1, Aq2, Aq3);

        #pragma unroll 1
        for (int k2 = 0; k2 < 64; ++k2) {
            {   const int k = 2 * k2;
                issueF(k + 3);
                cp_wait2(); __syncwarp();
                gatherF(k + 1, Bqb, Bq0, Bq1, Bq2, Bq3);
                stepF(Aqb, Aq0, Aq1, Aq2, Aq3);
            }
            {   const int k = 2 * k2 + 1;
                issueF(k + 3);
                cp_wait2(); __syncwarp();
                if (k2 < 63) gatherF(k + 1, Aqb, Aq0, Aq1, Aq2, Aq3);
                stepF(Bqb, Bq0, Bq1, Bq2, Bq3);
                renormF();   // every 8 steps
            }
        }
    } else {
        // ================= BACKWARD: frames 1023..512 -> beta_511 =================
        const float al1f = (y1 != y0) ? 1.f : 0.f;
        const float al2f = (y2 != y1) ? 1.f : 0.f;
        const float al3f = (y3 != y2) ? 1.f : 0.f;
        const int   ynx  = (l < 31) ? Y[4 * l + 4] : 0;
        const float alnf = ((l < 31) && (ynx != y3)) ? 1.f : 0.f;

        if (l == 31) { L3 = 1.f; b4 = 1.f; }
        E = (l == 31) ? 0 : SENT;

        #pragma unroll
        for (int g = 0; g < 3; ++g) {
            #pragma unroll
            for (int j = 0; j < 4; ++j) {
                const int f = 1023 - (g * 4 + j);
                cp_async16(rbase_sh + (uint32_t)(f & (RING - 1)) * (C_DIM * 4) + lane_off,
                           P + (size_t)f * C_DIM + l * 4);
            }
            cp_commit();
        }

        float Aqb[4], Aq0[4], Aq1[4], Aq2[4], Aq3[4], Aqn[4];
        float Bqb[4], Bq0[4], Bq1[4], Bq2[4], Bq3[4], Bqn[4];

        auto gatherB = [&](int kk, float (&qb)[4], float (&q0)[4], float (&q1)[4],
                           float (&q2)[4], float (&q3)[4], float (&qn)[4]) {
            #pragma unroll
            for (int j = 0; j < 4; ++j) {
                const float* r = ring[(1023 - (4 * kk + j)) & (RING - 1)];
                qb[j] = r[BLANK] + EPSV;
                q0[j] = r[y0] + EPSV;
                q1[j] = r[y1] + EPSV;
                q2[j] = r[y2] + EPSV;
                q3[j] = r[y3] + EPSV;
            }
            // qn (prob of next lane's first label) == neighbor's q0
            #pragma unroll
            for (int j = 0; j < 4; ++j)
                qn[j] = __shfl_down_sync(0xffffffffu, q0[j], 1);
        };
        auto stepB = [&](const float (&qb)[4], const float (&q0)[4], const float (&q1)[4],
                         const float (&q2)[4], const float (&q3)[4], const float (&qn)[4]) {
            #pragma unroll
            for (int j = 0; j < 4; ++j) {
                const float sqb = scale_in * qb[j];
                const float sqn = scale_in * qn[j];
                const float bn = __shfl_down_sync(0xffffffffu, b0, 1);
                const float Ln = __shfl_down_sync(0xffffffffu, L0, 1);

                const float gb0 = b0 * qb[j], gb1 = b1 * qb[j];
                const float gb2 = b2 * qb[j], gb3 = b3 * qb[j];
                const float gb4 = b4 * qb[j];
                const float gL0 = L0 * q0[j], gL1 = L1 * q1[j];
                const float gL2 = L2 * q2[j], gL3 = L3 * q3[j];
                const float gbn = bn * sqb;   // lane31: scale_in==0 -> vanishes
                const float gLn = Ln * sqn;

                const float nb0 = gb0 + gL0;
                const float nb1 = gb1 + gL1;
                const float nb2 = gb2 + gL2;
                const float nb3 = gb3 + gL3;
                const float nL0 = __fmaf_rn(al1f, gL1, gL0 + gb1);
                const float nL1 = __fmaf_rn(al2f, gL2, gL1 + gb2);
                const float nL2 = __fmaf_rn(al3f, gL3, gL2 + gb3);
                const float nL3 = __fmaf_rn(alnf, gLn, gL3 + gbn + gb4);

                L0 = nL0; L1 = nL1; L2 = nL2; L3 = nL3;
                b0 = nb0; b1 = nb1; b2 = nb2; b3 = nb3; b4 = gb4;
            }
        };
        auto renormB = [&]() {
            const float m = fmaxf(fmaxf(fmaxf(L0, L1), fmaxf(L2, L3)),
                                  fmaxf(fmaxf(b0, b1), fmaxf(b2, fmaxf(b3, b4))));
            int Ep = SENT;
            if (m > 0.f) Ep = E + ((__float_as_int(m) >> 23) & 255) - 127;
            const int t1 = __shfl_down_sync(0xffffffffu, Ep, 1);
            int F = (l <= 30) ? max(Ep, t1 - DECAY) : Ep;
            const int t2 = __shfl_down_sync(0xffffffffu, F, 2);
            if (l <= 29) F = max(F, t2 - 2 * DECAY);
            const int Fnb = __shfl_down_sync(0xffffffffu, F, 1);
            const float sc = pow2f(E - F);
            L0 *= sc; L1 *= sc; L2 *= sc; L3 *= sc;
            b0 *= sc; b1 *= sc; b2 *= sc; b3 *= sc; b4 *= sc;
            E = F;
            scale_in = (l == 31) ? 0.f : pow2f(Fnb - F);
        };
        auto issueB = [&](int kk) {
            const int i0 = 4 * kk;
            if (i0 < HALF_T) {
                #pragma unroll
                for (int j = 0; j < 4; ++j) {
                    const int f = 1023 - (i0 + j);
                    cp_async16(rbase_sh + (uint32_t)(f & (RING - 1)) * (C_DIM * 4) + lane_off,
                               P + (size_t)f * C_DIM + l * 4);
                }
            }
            cp_commit();
        };

        cp_wait2(); __syncwarp();
        gatherB(0, Aqb, Aq0, Aq1, Aq2, Aq3, Aqn);

        #pragma unroll 1
        for (int k2 = 0; k2 < 64; ++k2) {
            {   const int k = 2 * k2;
                issueB(k + 3);
                cp_wait2(); __syncwarp();
                gatherB(k + 1, Bqb, Bq0, Bq1, Bq2, Bq3, Bqn);
                stepB(Aqb, Aq0, Aq1, Aq2, Aq3, Aqn);
            }
            {   const int k = 2 * k2 + 1;
                issueB(k + 3);
                cp_wait2(); __syncwarp();
                if (k2 < 63) gatherB(k + 1, Aqb, Aq0, Aq1, Aq2, Aq3, Aqn);
                stepB(Bqb, Bq0, Bq1, Bq2, Bq3, Bqn);
                renormB();   // every 8 steps
            }
        }
    }

    // Publish boundary state to shared staging.
    float* dst = s_vals[wid][l];
    dst[0] = b0; dst[1] = b1; dst[2] = b2; dst[3] = b3;
    dst[4] = L0; dst[5] = L1; dst[6] = L2; dst[7] = L3;
    dst[8] = b4;
    s_exps[wid][l] = E;

    __syncthreads();

    // Warps 0 and 2 combine their (fwd,bwd) pair: ll = sum_s alpha*beta.
    if ((wid & 1) == 0) {
        const float* a = s_vals[wid][l];
        const float* c = s_vals[wid + 1][l];
        float s = 0.f;
        #pragma unroll
        for (int i = 0; i < 9; ++i) s += a[i] * c[i];
        int X = s_exps[wid][l] + s_exps[wid + 1][l];
        if (!(s > 0.f)) { s = 0.f; X = SENT * 2; }

        int M = X;
        #pragma unroll
        for (int off = 16; off; off >>= 1)
            M = max(M, __shfl_xor_sync(0xffffffffu, M, off));

        float v = s * pow2f(X - M);
        #pragma unroll
        for (int off = 16; off; off >>= 1)
            v += __shfl_xor_sync(0xffffffffu, v, off);

        if (l == 0)
            out[b] = (float)(-((double)M * 0.6931471805599453 + log((double)v)));
    }
}

extern "C" void kernel_launch(void* const* d_in, const int* in_sizes, int n_in,
                              void* d_out, int out_size)
{
    const int*   y_true = (const int*)d_in[0];
    const float* y_pred = (const float*)d_in[1];
    float*       out    = (float*)d_out;
    ctc_fused_kernel<<<B_DIM / 2, 128>>>(y_true, y_pred, out);
}